// round 2
// baseline (speedup 1.0000x reference)
#include <cuda_runtime.h>
#include <math.h>

#define BB 512
#define TT 2048
#define CC 64

__device__ int   g_i0[TT];
__device__ float g_w0[TT];
__device__ float g_w1[TT];
__device__ float g_ca[BB];
__device__ float g_sa[BB];
__device__ float g_mask[CC];

// One-block prep with parallel scan (no serial 256-iter chain).
__global__ void __launch_bounds__(512) prep_kernel(
    const float* __restrict__ scale_u,
    const float* __restrict__ warp_noise,
    const float* __restrict__ angle_u,
    const float* __restrict__ chmask_u)
{
    __shared__ float cum[TT];
    __shared__ float wsum[8];
    const int tid  = threadIdx.x;         // 512 threads
    const int lane = tid & 31;
    const int wid  = tid >> 5;
    const float k = 0.2f / (float)TT;     // TW_SIGMA / T

    float loc[8];
    float myTotal = 0.f, inc = 0.f;
    if (tid < 256) {
        float run = 0.f;
        #pragma unroll
        for (int i = 0; i < 8; i++) {
            run += warp_noise[tid * 8 + i] * k;
            loc[i] = run;
        }
        myTotal = run;
        // warp-inclusive scan of chunk totals
        inc = myTotal;
        #pragma unroll
        for (int d = 1; d < 32; d <<= 1) {
            float o = __shfl_up_sync(0xffffffffu, inc, d);
            if (lane >= d) inc += o;
        }
        if (lane == 31) wsum[wid] = inc;   // warp total (wid 0..7)
    }
    __syncthreads();
    if (tid == 0) {
        float a = 0.f;
        #pragma unroll
        for (int j = 0; j < 8; j++) { float v = wsum[j]; wsum[j] = a; a += v; }
    }
    __syncthreads();
    if (tid < 256) {
        float excl = (inc - myTotal) + wsum[wid];   // exclusive prefix of this chunk
        #pragma unroll
        for (int i = 0; i < 8; i++) cum[tid * 8 + i] = excl + loc[i];
    }
    __syncthreads();

    const float c0    = cum[0];
    const float denom = (cum[TT - 1] - c0) + 1e-8f;
    const float scale = 0.9f + scale_u[0] * 0.2f;

    if (tid < 256) {
        #pragma unroll
        for (int i = 0; i < 8; i++) {
            int t = tid * 8 + i;
            float w  = (cum[t] - c0) / denom;
            float tw = (float)t / (float)(TT - 1) + 0.2f * w;
            tw = fminf(fmaxf(tw, 0.f), 1.f);
            float pos = tw * (float)(TT - 1);
            int i0 = (int)floorf(pos);
            i0 = min(max(i0, 0), TT - 2);
            float frac = pos - (float)i0;
            g_i0[t] = i0;
            g_w0[t] = scale * (1.f - frac);
            g_w1[t] = scale * frac;
        }
    }

    {   // per-batch rotation (512 threads == B)
        float ang = angle_u[tid] * 6.283185307179586f - 3.141592653589793f;
        g_ca[tid] = cosf(ang);
        g_sa[tid] = sinf(ang);
    }
    if (tid < CC) g_mask[tid] = (chmask_u[tid] > 0.1f) ? 1.f : 0.f;
}

// Fused main pass: 8 threads per (b,t) row, each thread 2 float4 (8 channels).
// 8 front-batched LDG.128 per thread for high MLP; streaming store.
__global__ void __launch_bounds__(256) aug_kernel(
    const float4* __restrict__ x,
    const float4* __restrict__ nz,
    float4* __restrict__ out)
{
    const int gid  = blockIdx.x * 256 + threadIdx.x;
    const int row  = gid >> 3;            // b*T + t
    const int lane = gid & 7;             // which pair of float4s in the row
    const int t    = row & (TT - 1);
    const int b    = row >> 11;           // T = 2048 = 2^11

    const int   i0 = g_i0[t];
    const float w0 = g_w0[t];
    const float w1 = g_w1[t];

    const size_t base = ((size_t)b * TT + (size_t)i0) * 16 + (size_t)(lane * 2);
    const float4 x0a = __ldg(x  + base);
    const float4 x0b = __ldg(x  + base + 1);
    const float4 x1a = __ldg(x  + base + 16);
    const float4 x1b = __ldg(x  + base + 17);
    const float4 n0a = __ldg(nz + base);
    const float4 n0b = __ldg(nz + base + 1);
    const float4 n1a = __ldg(nz + base + 16);
    const float4 n1b = __ldg(nz + base + 17);

    const float J = 0.01f;
    float4 va, vb;
    va.x = w0 * fmaf(J, n0a.x, x0a.x) + w1 * fmaf(J, n1a.x, x1a.x);
    va.y = w0 * fmaf(J, n0a.y, x0a.y) + w1 * fmaf(J, n1a.y, x1a.y);
    va.z = w0 * fmaf(J, n0a.z, x0a.z) + w1 * fmaf(J, n1a.z, x1a.z);
    va.w = w0 * fmaf(J, n0a.w, x0a.w) + w1 * fmaf(J, n1a.w, x1a.w);
    vb.x = w0 * fmaf(J, n0b.x, x0b.x) + w1 * fmaf(J, n1b.x, x1b.x);
    vb.y = w0 * fmaf(J, n0b.y, x0b.y) + w1 * fmaf(J, n1b.y, x1b.y);
    vb.z = w0 * fmaf(J, n0b.z, x0b.z) + w1 * fmaf(J, n1b.z, x1b.z);
    vb.w = w0 * fmaf(J, n0b.w, x0b.w) + w1 * fmaf(J, n1b.w, x1b.w);

    if (lane == 0) {  // channels 0,1 rotation
        const float ca = g_ca[b], sa = g_sa[b];
        const float r0 = ca * va.x - sa * va.y;
        const float r1 = sa * va.x + ca * va.y;
        va.x = r0; va.y = r1;
    }

    const float4 ma = reinterpret_cast<const float4*>(g_mask)[lane * 2];
    const float4 mb = reinterpret_cast<const float4*>(g_mask)[lane * 2 + 1];
    va.x *= ma.x; va.y *= ma.y; va.z *= ma.z; va.w *= ma.w;
    vb.x *= mb.x; vb.y *= mb.y; vb.z *= mb.z; vb.w *= mb.w;

    const size_t ob = (size_t)row * 16 + (size_t)(lane * 2);
    __stcs(out + ob,     va);
    __stcs(out + ob + 1, vb);
}

extern "C" void kernel_launch(void* const* d_in, const int* in_sizes, int n_in,
                              void* d_out, int out_size)
{
    const float* x        = (const float*)d_in[0];
    const float* noise    = (const float*)d_in[1];
    const float* scale_u  = (const float*)d_in[2];
    const float* warp_n   = (const float*)d_in[3];
    const float* angle_u  = (const float*)d_in[4];
    const float* chmask_u = (const float*)d_in[5];
    float* out = (float*)d_out;

    prep_kernel<<<1, 512>>>(scale_u, warp_n, angle_u, chmask_u);

    // B*T*8 threads (each thread covers 8 channels)
    const int total_threads = BB * TT * 8;
    aug_kernel<<<total_threads / 256, 256>>>(
        (const float4*)x, (const float4*)noise, (float4*)out);
}

// round 5
// speedup vs baseline: 1.1891x; 1.1891x over previous
#include <cuda_runtime.h>
#include <math.h>

#define BB 512
#define TT 2048
#define CC 64

__device__ int   g_i0[TT];
__device__ float g_w0[TT];
__device__ float g_w1[TT];
__device__ float g_ca[BB];
__device__ float g_sa[BB];
__device__ float g_mask[CC];

// One-block prep with parallel scan.
__global__ void __launch_bounds__(512) prep_kernel(
    const float* __restrict__ scale_u,
    const float* __restrict__ warp_noise,
    const float* __restrict__ angle_u,
    const float* __restrict__ chmask_u)
{
    __shared__ float cum[TT];
    __shared__ float wsum[8];
    const int tid  = threadIdx.x;         // 512 threads
    const int lane = tid & 31;
    const int wid  = tid >> 5;
    const float k = 0.2f / (float)TT;     // TW_SIGMA / T

    float loc[8];
    float myTotal = 0.f, inc = 0.f;
    if (tid < 256) {
        float run = 0.f;
        #pragma unroll
        for (int i = 0; i < 8; i++) {
            run += warp_noise[tid * 8 + i] * k;
            loc[i] = run;
        }
        myTotal = run;
        inc = myTotal;
        #pragma unroll
        for (int d = 1; d < 32; d <<= 1) {
            float o = __shfl_up_sync(0xffffffffu, inc, d);
            if (lane >= d) inc += o;
        }
        if (lane == 31) wsum[wid] = inc;
    }
    __syncthreads();
    if (tid == 0) {
        float a = 0.f;
        #pragma unroll
        for (int j = 0; j < 8; j++) { float v = wsum[j]; wsum[j] = a; a += v; }
    }
    __syncthreads();
    if (tid < 256) {
        float excl = (inc - myTotal) + wsum[wid];
        #pragma unroll
        for (int i = 0; i < 8; i++) cum[tid * 8 + i] = excl + loc[i];
    }
    __syncthreads();

    const float c0    = cum[0];
    const float denom = (cum[TT - 1] - c0) + 1e-8f;
    const float scale = 0.9f + scale_u[0] * 0.2f;

    if (tid < 256) {
        #pragma unroll
        for (int i = 0; i < 8; i++) {
            int t = tid * 8 + i;
            float w  = (cum[t] - c0) / denom;
            float tw = (float)t / (float)(TT - 1) + 0.2f * w;
            tw = fminf(fmaxf(tw, 0.f), 1.f);
            float pos = tw * (float)(TT - 1);
            int i0 = (int)floorf(pos);
            i0 = min(max(i0, 0), TT - 2);
            float frac = pos - (float)i0;
            g_i0[t] = i0;
            g_w0[t] = scale * (1.f - frac);
            g_w1[t] = scale * frac;
        }
    }

    {   // per-batch rotation (512 threads == B)
        float ang = angle_u[tid] * 6.283185307179586f - 3.141592653589793f;
        g_ca[tid] = cosf(ang);
        g_sa[tid] = sinf(ang);
    }
    if (tid < CC) g_mask[tid] = (chmask_u[tid] > 0.1f) ? 1.f : 0.f;
}

// Fused main pass: 16 contiguous threads per 64-channel row (fully coalesced
// float4 accesses), each thread processes TWO adjacent t-rows of the same
// batch -> 8 front-batched coalesced LDG.128 per thread (high MLP).
__global__ void __launch_bounds__(256) aug_kernel(
    const float4* __restrict__ x,
    const float4* __restrict__ nz,
    float4* __restrict__ out)
{
    const int gid   = blockIdx.x * 256 + threadIdx.x;
    const int lane  = gid & 15;           // float4 index within row
    const int p     = gid >> 4;           // row-pair index
    const int row0  = p * 2;              // b*T + t0 (t0 even)
    const int t0    = row0 & (TT - 1);
    const int t1    = t0 + 1;
    const int b     = row0 >> 11;         // T = 2048 = 2^11

    const int   i0a = g_i0[t0];
    const int   i0b = g_i0[t1];
    const float w0a = g_w0[t0], w1a = g_w1[t0];
    const float w0b = g_w0[t1], w1b = g_w1[t1];

    const size_t bb    = (size_t)b * TT;
    const size_t baseA = (bb + (size_t)i0a) * 16 + (size_t)lane;
    const size_t baseB = (bb + (size_t)i0b) * 16 + (size_t)lane;

    // 8 independent coalesced 128-bit loads, front-batched for MLP
    const float4 xa0 = __ldg(x  + baseA);
    const float4 xa1 = __ldg(x  + baseA + 16);
    const float4 xb0 = __ldg(x  + baseB);
    const float4 xb1 = __ldg(x  + baseB + 16);
    const float4 na0 = __ldg(nz + baseA);
    const float4 na1 = __ldg(nz + baseA + 16);
    const float4 nb0 = __ldg(nz + baseB);
    const float4 nb1 = __ldg(nz + baseB + 16);

    const float J = 0.01f;
    float4 va, vb;
    va.x = w0a * fmaf(J, na0.x, xa0.x) + w1a * fmaf(J, na1.x, xa1.x);
    va.y = w0a * fmaf(J, na0.y, xa0.y) + w1a * fmaf(J, na1.y, xa1.y);
    va.z = w0a * fmaf(J, na0.z, xa0.z) + w1a * fmaf(J, na1.z, xa1.z);
    va.w = w0a * fmaf(J, na0.w, xa0.w) + w1a * fmaf(J, na1.w, xa1.w);
    vb.x = w0b * fmaf(J, nb0.x, xb0.x) + w1b * fmaf(J, nb1.x, xb1.x);
    vb.y = w0b * fmaf(J, nb0.y, xb0.y) + w1b * fmaf(J, nb1.y, xb1.y);
    vb.z = w0b * fmaf(J, nb0.z, xb0.z) + w1b * fmaf(J, nb1.z, xb1.z);
    vb.w = w0b * fmaf(J, nb0.w, xb0.w) + w1b * fmaf(J, nb1.w, xb1.w);

    if (lane == 0) {  // channels 0,1 rotation (both rows, same batch)
        const float ca = g_ca[b], sa = g_sa[b];
        float r0 = ca * va.x - sa * va.y;
        float r1 = sa * va.x + ca * va.y;
        va.x = r0; va.y = r1;
        r0 = ca * vb.x - sa * vb.y;
        r1 = sa * vb.x + ca * vb.y;
        vb.x = r0; vb.y = r1;
    }

    const float4 m = reinterpret_cast<const float4*>(g_mask)[lane];
    va.x *= m.x; va.y *= m.y; va.z *= m.z; va.w *= m.w;
    vb.x *= m.x; vb.y *= m.y; vb.z *= m.z; vb.w *= m.w;

    const size_t ob = (size_t)row0 * 16 + (size_t)lane;
    __stcs(out + ob,      va);
    __stcs(out + ob + 16, vb);
}

extern "C" void kernel_launch(void* const* d_in, const int* in_sizes, int n_in,
                              void* d_out, int out_size)
{
    const float* x        = (const float*)d_in[0];
    const float* noise    = (const float*)d_in[1];
    const float* scale_u  = (const float*)d_in[2];
    const float* warp_n   = (const float*)d_in[3];
    const float* angle_u  = (const float*)d_in[4];
    const float* chmask_u = (const float*)d_in[5];
    float* out = (float*)d_out;

    prep_kernel<<<1, 512>>>(scale_u, warp_n, angle_u, chmask_u);

    // B*T/2 row-pairs * 16 threads each
    const int total_threads = BB * TT * 8;
    aug_kernel<<<total_threads / 256, 256>>>(
        (const float4*)x, (const float4*)noise, (float4*)out);
}